// round 3
// baseline (speedup 1.0000x reference)
#include <cuda_runtime.h>
#include <math_constants.h>

typedef unsigned long long u64;

// Problem constants
#define Bk 2
#define Lk 2048
#define Sk 2048
#define Hk 8
#define Ek 64
#define Dk 64
#define NBH (Bk*Hk)

// Tiling
#define TQ 64
#define TS 128
#define NTHREADS 256

// Smem row strides (floats)
#define QDP 132   // sQd: [64 q][2e dup]   (aligned 16B rows)
#define KTP 132   // sKT: [64 e][128 s]+pad
#define VDP 132   // sVd: [128 s][2d dup]
#define PP  68    // sP : [128 s][64 q]

#define SMEM_FLOATS (64*QDP + 64*KTP + 128*VDP + 128*PP)
#define SMEM_BYTES  (SMEM_FLOATS * 4)

// Scratch (static device globals: no runtime allocation allowed)
__device__ float g_Otmp[(size_t)NBH * Lk * Dk];            // [bh][l][d]
__device__ unsigned long long g_Key[NBH * Lk];             // packed sort key

// ---- packed f32x2 helpers ----
__device__ __forceinline__ void fma2(u64& d, u64 a, u64 b) {
    asm("fma.rn.f32x2 %0, %1, %2, %0;" : "+l"(d) : "l"(a), "l"(b));
}
__device__ __forceinline__ void mul2(u64& d, u64 a) {
    asm("mul.rn.f32x2 %0, %0, %1;" : "+l"(d) : "l"(a));
}
__device__ __forceinline__ u64 add2(u64 a, u64 b) {
    u64 r; asm("add.rn.f32x2 %0, %1, %2;" : "=l"(r) : "l"(a), "l"(b)); return r;
}
__device__ __forceinline__ u64 pack2(float x, float y) {
    u64 r; asm("mov.b64 %0, {%1, %2};" : "=l"(r) : "f"(x), "f"(y)); return r;
}
__device__ __forceinline__ float2 unpack2(u64 v) {
    float2 r; asm("mov.b64 {%0, %1}, %2;" : "=f"(r.x), "=f"(r.y) : "l"(v)); return r;
}

// ---------------------------------------------------------------------------
// Kernel 1: fused flash attention + sparsity stats, packed-f32x2 GEMMs.
// CTA = (b,h) x 64-query tile; 256 threads = 16(tq) x 16(ts).
// GEMM1: thread (tq,ts) computes rows 4tq..+3 vs key pairs s=(2ts+32k, +1).
// GEMM2: pairs over query rows: acc2[a][j] = rows (4tq+2a, +1), col 4ts+j.
// ---------------------------------------------------------------------------
__global__ __launch_bounds__(NTHREADS, 1)
void k_attn(const float* __restrict__ Qg,
            const float* __restrict__ Kg,
            const float* __restrict__ Vg)
{
    extern __shared__ float smem[];
    float* sQd = smem;                 // [64][QDP]  (q, dup e)
    float* sKT = sQd + 64*QDP;         // [64][KTP]  (e, s)
    float* sVd = sKT + 64*KTP;         // [128][VDP] (s, dup d)
    float* sP  = sVd + 128*VDP;        // [128][PP]  (s, q)

    const int tile = blockIdx.x & 31;
    const int bh   = blockIdx.x >> 5;
    const int b = bh >> 3, h = bh & 7;
    const int q0 = tile * TQ;
    const int tid = threadIdx.x;
    const int tq = tid >> 4;
    const int ts = tid & 15;

    const float* Qbase = Qg + ((b*Lk + q0) * Hk + h) * Ek;
    const float* Kbase = Kg + (b*Sk*Hk + h) * Ek;
    const float* Vbase = Vg + (b*Sk*Hk + h) * Dk;

    // Load Q tile duplicated: sQd[r][2c..] = {x,x,y,y,z,z,w,w}
    #pragma unroll
    for (int i = 0; i < 4; i++) {
        int idx = tid + i * NTHREADS;
        int r = idx >> 4, c = (idx & 15) * 4;
        float4 v4 = *(const float4*)(Qbase + r * (Hk*Ek) + c);
        *(float4*)(sQd + r*QDP + 2*c)     = make_float4(v4.x, v4.x, v4.y, v4.y);
        *(float4*)(sQd + r*QDP + 2*c + 4) = make_float4(v4.z, v4.z, v4.w, v4.w);
    }

    u64 acc2[2][4];
    float m[4], den[4], rsum[4];
    #pragma unroll
    for (int a = 0; a < 2; a++)
        #pragma unroll
        for (int j = 0; j < 4; j++) acc2[a][j] = 0ull;
    #pragma unroll
    for (int i = 0; i < 4; i++) { m[i] = -CUDART_INF_F; den[i] = 0.f; rsum[i] = 0.f; }

    for (int s0 = 0; s0 < Sk; s0 += TS) {
        __syncthreads();   // previous chunk's GEMM2 done before overwriting K/V
        // Load K transposed + V duplicated
        #pragma unroll
        for (int i = 0; i < 8; i++) {
            int idx = tid + i * NTHREADS;
            int r = idx >> 4, c = (idx & 15) * 4;     // r = s row, c = col base
            float4 kv = *(const float4*)(Kbase + (s0 + r) * (Hk*Ek) + c);
            sKT[(c+0)*KTP + r] = kv.x;
            sKT[(c+1)*KTP + r] = kv.y;
            sKT[(c+2)*KTP + r] = kv.z;
            sKT[(c+3)*KTP + r] = kv.w;
            float4 vv = *(const float4*)(Vbase + (s0 + r) * (Hk*Dk) + c);
            *(float4*)(sVd + r*VDP + 2*c)     = make_float4(vv.x, vv.x, vv.y, vv.y);
            *(float4*)(sVd + r*VDP + 2*c + 4) = make_float4(vv.z, vv.z, vv.w, vv.w);
        }
        __syncthreads();

        // GEMM1: sc2[i][k] = packed scores for row 4tq+i, keys (2ts+32k, +1)
        u64 sc2[4][4];
        #pragma unroll
        for (int i = 0; i < 4; i++)
            #pragma unroll
            for (int k = 0; k < 4; k++) sc2[i][k] = 0ull;

        #pragma unroll 4
        for (int e = 0; e < Ek; e++) {
            u64 qq[4], kk[4];
            #pragma unroll
            for (int i = 0; i < 4; i++)
                qq[i] = *(const u64*)(sQd + (4*tq + i)*QDP + 2*e);
            #pragma unroll
            for (int k = 0; k < 4; k++)
                kk[k] = *(const u64*)(sKT + e*KTP + 2*ts + 32*k);
            #pragma unroll
            for (int i = 0; i < 4; i++)
                #pragma unroll
                for (int k = 0; k < 4; k++)
                    fma2(sc2[i][k], qq[i], kk[k]);
        }

        // Per-row stats + online softmax update (16 ts lanes per row group)
        float scale_row[4];
        #pragma unroll
        for (int i = 0; i < 4; i++) {
            float2 sv[4];
            #pragma unroll
            for (int k = 0; k < 4; k++) sv[k] = unpack2(sc2[i][k]);
            u64 csum2 = add2(add2(sc2[i][0], sc2[i][1]), add2(sc2[i][2], sc2[i][3]));
            float2 cs = unpack2(csum2);
            float csum = cs.x + cs.y;
            float cmax = fmaxf(fmaxf(fmaxf(sv[0].x, sv[0].y), fmaxf(sv[1].x, sv[1].y)),
                               fmaxf(fmaxf(sv[2].x, sv[2].y), fmaxf(sv[3].x, sv[3].y)));
            #pragma unroll
            for (int o = 1; o < 16; o <<= 1) {
                cmax = fmaxf(cmax, __shfl_xor_sync(0xffffffffu, cmax, o));
                csum += __shfl_xor_sync(0xffffffffu, csum, o);
            }
            rsum[i] += csum;
            float mnew  = fmaxf(m[i], cmax);
            scale_row[i] = __expf((m[i] - mnew) * 0.125f);
            den[i] *= scale_row[i];
            m[i] = mnew;

            float psum = 0.f;
            #pragma unroll
            for (int k = 0; k < 4; k++) {
                int s = 2*ts + 32*k;
                float p0 = __expf((sv[k].x - mnew) * 0.125f);
                float p1 = __expf((sv[k].y - mnew) * 0.125f);
                psum += p0 + p1;
                sP[(s+0)*PP + 4*tq + i] = p0;
                sP[(s+1)*PP + 4*tq + i] = p1;
            }
            #pragma unroll
            for (int o = 1; o < 16; o <<= 1)
                psum += __shfl_xor_sync(0xffffffffu, psum, o);
            den[i] += psum;
        }
        // Rescale accumulators (packed per row-pair)
        u64 sp0 = pack2(scale_row[0], scale_row[1]);
        u64 sp1 = pack2(scale_row[2], scale_row[3]);
        #pragma unroll
        for (int j = 0; j < 4; j++) { mul2(acc2[0][j], sp0); mul2(acc2[1][j], sp1); }
        __syncthreads();

        // GEMM2: acc2[a][j] += P(s, rows 4tq+2a,+1) * V(s, 4ts+j) (dup)
        #pragma unroll 4
        for (int s = 0; s < TS; s++) {
            u64 pp0 = *(const u64*)(sP + s*PP + 4*tq);
            u64 pp1 = *(const u64*)(sP + s*PP + 4*tq + 2);
            ulonglong2 w0 = *(const ulonglong2*)(sVd + s*VDP + 8*ts);      // (v0,v0),(v1,v1)
            ulonglong2 w1 = *(const ulonglong2*)(sVd + s*VDP + 8*ts + 4);  // (v2,v2),(v3,v3)
            fma2(acc2[0][0], pp0, w0.x);
            fma2(acc2[0][1], pp0, w0.y);
            fma2(acc2[0][2], pp0, w1.x);
            fma2(acc2[0][3], pp0, w1.y);
            fma2(acc2[1][0], pp1, w0.x);
            fma2(acc2[1][1], pp1, w0.y);
            fma2(acc2[1][2], pp1, w1.x);
            fma2(acc2[1][3], pp1, w1.y);
        }
    }

    // Epilogue: normalized output rows + packed rank key
    float* Obase = g_Otmp + ((size_t)bh * Lk + q0) * Dk;
    #pragma unroll
    for (int a = 0; a < 2; a++) {
        float inv0 = 1.0f / den[2*a + 0];
        float inv1 = 1.0f / den[2*a + 1];
        float4 o0, o1;
        float2 t0 = unpack2(acc2[a][0]);
        float2 t1 = unpack2(acc2[a][1]);
        float2 t2 = unpack2(acc2[a][2]);
        float2 t3 = unpack2(acc2[a][3]);
        o0.x = t0.x*inv0; o0.y = t1.x*inv0; o0.z = t2.x*inv0; o0.w = t3.x*inv0;
        o1.x = t0.y*inv1; o1.y = t1.y*inv1; o1.z = t2.y*inv1; o1.w = t3.y*inv1;
        *(float4*)(Obase + (4*tq + 2*a + 0)*Dk + 4*ts) = o0;
        *(float4*)(Obase + (4*tq + 2*a + 1)*Dk + 4*ts) = o1;
    }
    if (ts == 0) {
        #pragma unroll
        for (int i = 0; i < 4; i++) {
            float msp = m[i] - rsum[i] * (1.0f / (float)Sk);
            int bi = __float_as_int(msp);
            unsigned u = (unsigned)bi ^ ((bi < 0) ? 0xFFFFFFFFu : 0x80000000u);
            int l = q0 + 4*tq + i;
            g_Key[bh*Lk + l] = ((unsigned long long)u << 32) | (unsigned)(~l);
        }
    }
}

// ---------------------------------------------------------------------------
// Kernel 2: rank via counting on packed u64 keys + fused scatter.
// ---------------------------------------------------------------------------
#define RROWS 256
__global__ __launch_bounds__(256)
void k_rank_scatter(float* __restrict__ out)
{
    __shared__ unsigned long long sKey[Lk];
    __shared__ int sR[RROWS];
    const int slice = blockIdx.x & 7;
    const int bh    = blockIdx.x >> 3;
    const int b = bh >> 3, h = bh & 7;
    const int t = threadIdx.x;
    const int base = slice * RROWS;

    for (int i = t; i < Lk; i += 256)
        sKey[i] = g_Key[bh*Lk + i];
    __syncthreads();

    const unsigned long long my = sKey[base + t];
    int cnt = 0;
    #pragma unroll 8
    for (int j = 0; j < Lk; j++)
        cnt += (sKey[j] > my);
    sR[t] = cnt;
    __syncthreads();

    const float* src = g_Otmp + ((size_t)bh * Lk + base) * Dk;
    for (int w = t; w < RROWS * (Dk/4); w += 256) {
        int lr = w >> 4;
        int c  = (w & 15) * 4;
        float4 v = *(const float4*)(src + lr*Dk + c);
        int rr = sR[lr];
        *(float4*)(out + (((size_t)b*Lk + rr)*Hk + h)*Dk + c) = v;
    }
}

// ---------------------------------------------------------------------------
extern "C" void kernel_launch(void* const* d_in, const int* in_sizes, int n_in,
                              void* d_out, int out_size)
{
    (void)in_sizes; (void)n_in; (void)out_size;
    const float* Q = (const float*)d_in[0];
    const float* K = (const float*)d_in[1];
    const float* V = (const float*)d_in[2];
    float* out = (float*)d_out;

    cudaFuncSetAttribute(k_attn, cudaFuncAttributeMaxDynamicSharedMemorySize, SMEM_BYTES);

    k_attn<<<NBH * (Lk / TQ), NTHREADS, SMEM_BYTES>>>(Q, K, V);
    k_rank_scatter<<<NBH * 8, 256>>>(out);
}

// round 6
// speedup vs baseline: 2.2319x; 2.2319x over previous
#include <cuda_runtime.h>
#include <cstdint>

typedef uint32_t u32;

// Problem constants
#define Bk 2
#define Lk 2048
#define Sk 2048
#define Hk 8
#define Ek 64
#define Dk 64
#define NBH (Bk*Hk)

#define TQ 128            // queries per CTA
#define TS 64             // keys per chunk
#define NCHUNK (Sk/TS)    // 32
#define NTHREADS 256

// smem row strides (floats)
#define QP 68
#define KP 72
#define VP 72
#define PP 68

// smem float offsets
#define O_QHI 0
#define O_QLO (O_QHI + TQ*QP)
#define O_KHI (O_QLO + TQ*QP)
#define O_KLO (O_KHI + TS*KP)
#define O_VHI (O_KLO + TS*KP)
#define O_VLO (O_VHI + TS*VP)
#define O_P   (O_VLO + TS*VP)
#define O_DEN (O_P + TQ*PP)
#define O_MX  (O_DEN + 2*TQ)
#define O_MXI (O_MX + 2*TQ)
#define O_INV (O_MXI + 2*TQ)
#define O_KS  (O_INV + TQ)       // [16][64] partials
#define O_KSUM (O_KS + 16*64)    // [64]
#define SMEM_FLOATS (O_KSUM + 64)
#define SMEM_BYTES  (SMEM_FLOATS * 4)

// Scratch
__device__ float g_Otmp[(size_t)NBH * Lk * Dk];
__device__ unsigned long long g_Key[NBH * Lk];

__device__ __forceinline__ float hi32(float x) {
    return __uint_as_float(__float_as_uint(x) & 0xFFFFE000u);
}

// m16n8k8 tf32 mma: D += A*B. a: 4 regs, b: 2 regs, d: 4 fp32.
__device__ __forceinline__ void mma8(float* d, const u32* a, u32 b0, u32 b1) {
    asm volatile(
        "mma.sync.aligned.m16n8k8.row.col.f32.tf32.tf32.f32 "
        "{%0,%1,%2,%3}, {%4,%5,%6,%7}, {%8,%9}, {%0,%1,%2,%3};"
        : "+f"(d[0]), "+f"(d[1]), "+f"(d[2]), "+f"(d[3])
        : "r"(a[0]), "r"(a[1]), "r"(a[2]), "r"(a[3]), "r"(b0), "r"(b1));
}

// ---------------------------------------------------------------------------
// Kernel 1: HMMA tf32 (3-term fp32-split) flash attention.
// Exact M_sp: mean via q.Ksum (Ksum accumulated during K loads),
// max via tf32-argmax + exact fp32 re-dot of the winning key.
// 8 warps = 4(m) x 2(n). Warp tile 32q x 32s / 32q x 32d.
// ---------------------------------------------------------------------------
__global__ __launch_bounds__(NTHREADS, 1)
void k_attn(const float* __restrict__ Qg,
            const float* __restrict__ Kg,
            const float* __restrict__ Vg)
{
    extern __shared__ float sm[];
    const int tile = blockIdx.x & 15;
    const int bh   = blockIdx.x >> 4;
    const int b = bh >> 3, h = bh & 7;
    const int q0 = tile * TQ;
    const int tid  = threadIdx.x;
    const int lane = tid & 31, wid = tid >> 5;
    const int wm = wid >> 1, wn = wid & 1;
    const int g = lane >> 2, tg = lane & 3;

    // ---- load + split Q tile (persistent, [q][e] hi/lo) ----
    #pragma unroll
    for (int i = 0; i < 8; i++) {
        int idx = tid + i * NTHREADS;
        int r = idx >> 4, c = (idx & 15) << 2;
        float4 v = *(const float4*)(Qg + ((size_t)((b*Lk + q0 + r)*Hk + h))*Ek + c);
        float e[4] = {v.x, v.y, v.z, v.w};
        #pragma unroll
        for (int j = 0; j < 4; j++) {
            float hi = hi32(e[j]);
            sm[O_QHI + r*QP + c + j] = hi;
            sm[O_QLO + r*QP + c + j] = e[j] - hi;
        }
    }

    float D2[2][4][4];
    #pragma unroll
    for (int mt = 0; mt < 2; mt++)
        #pragma unroll
        for (int nt = 0; nt < 4; nt++)
            #pragma unroll
            for (int r = 0; r < 4; r++) D2[mt][nt][r] = 0.f;

    float den_p[2][2] = {{0.f,0.f},{0.f,0.f}};
    float mx_p[2][2]  = {{-1e30f,-1e30f},{-1e30f,-1e30f}};
    int   mxi_p[2][2] = {{0,0},{0,0}};
    float ksum_r[4]   = {0.f,0.f,0.f,0.f};   // partial K column sums (cols c..c+3)

    for (int ch = 0; ch < NCHUNK; ch++) {
        const int s0 = ch * TS;
        __syncthreads();

        // ---- K chunk: load, accumulate Ksum, split, transpose to [e][s] ----
        #pragma unroll
        for (int i = 0; i < 4; i++) {
            int idx = tid + i * NTHREADS;
            int r = idx >> 4, c = (idx & 15) << 2;
            float4 v = *(const float4*)(Kg + ((size_t)((b*Sk + s0 + r)*Hk + h))*Ek + c);
            float e[4] = {v.x, v.y, v.z, v.w};
            #pragma unroll
            for (int j = 0; j < 4; j++) {
                ksum_r[j] += e[j];
                float hi = hi32(e[j]);
                sm[O_KHI + (c + j)*KP + r] = hi;
                sm[O_KLO + (c + j)*KP + r] = e[j] - hi;
            }
        }
        // ---- V chunk: load, split, [s][d] hi/lo ----
        #pragma unroll
        for (int i = 0; i < 4; i++) {
            int idx = tid + i * NTHREADS;
            int r = idx >> 4, c = (idx & 15) << 2;
            float4 v = *(const float4*)(Vg + ((size_t)((b*Sk + s0 + r)*Hk + h))*Dk + c);
            float e[4] = {v.x, v.y, v.z, v.w};
            #pragma unroll
            for (int j = 0; j < 4; j++) {
                float hi = hi32(e[j]);
                sm[O_VHI + r*VP + c + j] = hi;
                sm[O_VLO + r*VP + c + j] = e[j] - hi;
            }
        }
        __syncthreads();

        // ---- GEMM1: scores(q,s) = Q.K^T via 3-term split ----
        float D1[2][4][4];
        #pragma unroll
        for (int mt = 0; mt < 2; mt++)
            #pragma unroll
            for (int nt = 0; nt < 4; nt++)
                #pragma unroll
                for (int r = 0; r < 4; r++) D1[mt][nt][r] = 0.f;

        #pragma unroll
        for (int ks = 0; ks < 8; ks++) {
            const int e0 = ks << 3;
            u32 ahi[2][4], alo[2][4];
            #pragma unroll
            for (int mt = 0; mt < 2; mt++) {
                const int qr = 32*wm + 16*mt;
                ahi[mt][0] = __float_as_uint(sm[O_QHI + (qr+g  )*QP + e0 + tg]);
                ahi[mt][1] = __float_as_uint(sm[O_QHI + (qr+g+8)*QP + e0 + tg]);
                ahi[mt][2] = __float_as_uint(sm[O_QHI + (qr+g  )*QP + e0 + tg+4]);
                ahi[mt][3] = __float_as_uint(sm[O_QHI + (qr+g+8)*QP + e0 + tg+4]);
                alo[mt][0] = __float_as_uint(sm[O_QLO + (qr+g  )*QP + e0 + tg]);
                alo[mt][1] = __float_as_uint(sm[O_QLO + (qr+g+8)*QP + e0 + tg]);
                alo[mt][2] = __float_as_uint(sm[O_QLO + (qr+g  )*QP + e0 + tg+4]);
                alo[mt][3] = __float_as_uint(sm[O_QLO + (qr+g+8)*QP + e0 + tg+4]);
            }
            #pragma unroll
            for (int nt = 0; nt < 4; nt++) {
                const int scol = 32*wn + 8*nt;
                u32 bh0 = __float_as_uint(sm[O_KHI + (e0+tg  )*KP + scol + g]);
                u32 bh1 = __float_as_uint(sm[O_KHI + (e0+tg+4)*KP + scol + g]);
                u32 bl0 = __float_as_uint(sm[O_KLO + (e0+tg  )*KP + scol + g]);
                u32 bl1 = __float_as_uint(sm[O_KLO + (e0+tg+4)*KP + scol + g]);
                #pragma unroll
                for (int mt = 0; mt < 2; mt++) {
                    mma8(D1[mt][nt], ahi[mt], bh0, bh1);
                    mma8(D1[mt][nt], alo[mt], bh0, bh1);
                    mma8(D1[mt][nt], ahi[mt], bl0, bl1);
                }
            }
        }

        // ---- softmax + argmax/den stats + P -> smem ----
        #pragma unroll
        for (int mt = 0; mt < 2; mt++) {
            const int qr = 32*wm + 16*mt;
            #pragma unroll
            for (int nt = 0; nt < 4; nt++) {
                const int scol = 32*wn + 8*nt + 2*tg;
                const int sglob = s0 + scol;
                float s00 = D1[mt][nt][0], s01 = D1[mt][nt][1];
                float s10 = D1[mt][nt][2], s11 = D1[mt][nt][3];
                float m0 = fmaxf(s00, s01), m1 = fmaxf(s10, s11);
                if (m0 > mx_p[mt][0]) { mx_p[mt][0] = m0; mxi_p[mt][0] = sglob + (s01 > s00); }
                if (m1 > mx_p[mt][1]) { mx_p[mt][1] = m1; mxi_p[mt][1] = sglob + (s11 > s10); }
                float p00 = __expf(s00 * 0.125f), p01 = __expf(s01 * 0.125f);
                float p10 = __expf(s10 * 0.125f), p11 = __expf(s11 * 0.125f);
                den_p[mt][0] += p00 + p01;
                den_p[mt][1] += p10 + p11;
                *(float2*)(sm + O_P + (qr+g  )*PP + scol) = make_float2(p00, p01);
                *(float2*)(sm + O_P + (qr+g+8)*PP + scol) = make_float2(p10, p11);
            }
        }
        __syncthreads();

        // ---- GEMM2: D2 += P.V via 3-term split (P split in regs) ----
        #pragma unroll
        for (int ks = 0; ks < 8; ks++) {
            const int sb2 = ks << 3;
            u32 phi[2][4], plo[2][4];
            #pragma unroll
            for (int mt = 0; mt < 2; mt++) {
                const int qr = 32*wm + 16*mt;
                float p0 = sm[O_P + (qr+g  )*PP + sb2 + tg];
                float p1 = sm[O_P + (qr+g+8)*PP + sb2 + tg];
                float p2 = sm[O_P + (qr+g  )*PP + sb2 + tg+4];
                float p3 = sm[O_P + (qr+g+8)*PP + sb2 + tg+4];
                float h0 = hi32(p0), h1 = hi32(p1), h2 = hi32(p2), h3 = hi32(p3);
                phi[mt][0] = __float_as_uint(h0); plo[mt][0] = __float_as_uint(p0 - h0);
                phi[mt][1] = __float_as_uint(h1); plo[mt][1] = __float_as_uint(p1 - h1);
                phi[mt][2] = __float_as_uint(h2); plo[mt][2] = __float_as_uint(p2 - h2);
                phi[mt][3] = __float_as_uint(h3); plo[mt][3] = __float_as_uint(p3 - h3);
            }
            #pragma unroll
            for (int nt = 0; nt < 4; nt++) {
                const int dcol = 32*wn + 8*nt;
                u32 bh0 = __float_as_uint(sm[O_VHI + (sb2+tg  )*VP + dcol + g]);
                u32 bh1 = __float_as_uint(sm[O_VHI + (sb2+tg+4)*VP + dcol + g]);
                u32 bl0 = __float_as_uint(sm[O_VLO + (sb2+tg  )*VP + dcol + g]);
                u32 bl1 = __float_as_uint(sm[O_VLO + (sb2+tg+4)*VP + dcol + g]);
                #pragma unroll
                for (int mt = 0; mt < 2; mt++) {
                    mma8(D2[mt][nt], phi[mt], bh0, bh1);
                    mma8(D2[mt][nt], plo[mt], bh0, bh1);
                    mma8(D2[mt][nt], phi[mt], bl0, bl1);
                }
            }
        }
    }

    // ---- Ksum reduction: [16 row-groups][64 cols] -> Ksum[64] ----
    {
        int c = (tid & 15) << 2;
        *(float4*)(sm + O_KS + (tid >> 4)*64 + c) =
            make_float4(ksum_r[0], ksum_r[1], ksum_r[2], ksum_r[3]);
    }
    // ---- den/max/idx: reduce over tg lanes, publish per wn ----
    #pragma unroll
    for (int mt = 0; mt < 2; mt++)
        #pragma unroll
        for (int r = 0; r < 2; r++) {
            float d = den_p[mt][r], mx = mx_p[mt][r];
            int idx = mxi_p[mt][r];
            #pragma unroll
            for (int o = 1; o < 4; o <<= 1) {
                d += __shfl_xor_sync(0xffffffffu, d, o);
                float om = __shfl_xor_sync(0xffffffffu, mx, o);
                int   oi = __shfl_xor_sync(0xffffffffu, idx, o);
                if (om > mx) { mx = om; idx = oi; }
            }
            if (tg == 0) {
                int q = 32*wm + 16*mt + g + 8*r;
                sm[O_DEN + wn*TQ + q] = d;
                sm[O_MX  + wn*TQ + q] = mx;
                sm[O_MXI + wn*TQ + q] = __int_as_float(idx);
            }
        }
    __syncthreads();

    if (tid < 64) {
        float s = 0.f;
        #pragma unroll
        for (int gr = 0; gr < 16; gr++) s += sm[O_KS + gr*64 + tid];
        sm[O_KSUM + tid] = s;
    }
    __syncthreads();

    // ---- exact M_sp per query: refined max + q.Ksum mean ----
    if (tid < TQ) {
        const int q = tid;
        float den = sm[O_DEN + q] + sm[O_DEN + TQ + q];
        sm[O_INV + q] = 1.0f / den;
        float mx0 = sm[O_MX + q], mx1 = sm[O_MX + TQ + q];
        int idx = (mx1 > mx0) ? __float_as_int(sm[O_MXI + TQ + q])
                              : __float_as_int(sm[O_MXI + q]);
        const float* krow = Kg + ((size_t)((b*Sk + idx)*Hk + h))*Ek;
        float dot = 0.f, rs = 0.f;
        #pragma unroll 8
        for (int e = 0; e < Ek; e++) {
            float qv = sm[O_QHI + q*QP + e] + sm[O_QLO + q*QP + e];  // exact fp32
            dot = fmaf(qv, krow[e], dot);
            rs  = fmaf(qv, sm[O_KSUM + e], rs);
        }
        float msp = dot - rs * (1.0f / (float)Sk);
        int bi = __float_as_int(msp);
        unsigned u = (unsigned)bi ^ ((bi < 0) ? 0xFFFFFFFFu : 0x80000000u);
        int l = q0 + q;
        g_Key[bh*Lk + l] = ((unsigned long long)u << 32) | (unsigned)(~l);
    }
    __syncthreads();

    // ---- epilogue: normalize + write Otmp ----
    float* dst = g_Otmp + ((size_t)bh * Lk + q0) * Dk;
    #pragma unroll
    for (int mt = 0; mt < 2; mt++) {
        const int qr = 32*wm + 16*mt;
        float inv0 = sm[O_INV + qr + g];
        float inv1 = sm[O_INV + qr + g + 8];
        #pragma unroll
        for (int nt = 0; nt < 4; nt++) {
            const int dcol = 32*wn + 8*nt + 2*tg;
            *(float2*)(dst + (size_t)(qr+g  )*Dk + dcol) =
                make_float2(D2[mt][nt][0]*inv0, D2[mt][nt][1]*inv0);
            *(float2*)(dst + (size_t)(qr+g+8)*Dk + dcol) =
                make_float2(D2[mt][nt][2]*inv1, D2[mt][nt][3]*inv1);
        }
    }
}

// ---------------------------------------------------------------------------
// Kernel 2: rank via counting on packed u64 keys + fused scatter.
// ---------------------------------------------------------------------------
#define RROWS 256
__global__ __launch_bounds__(256)
void k_rank_scatter(float* __restrict__ out)
{
    __shared__ unsigned long long sKey[Lk];
    __shared__ int sR[RROWS];
    const int slice = blockIdx.x & 7;
    const int bh    = blockIdx.x >> 3;
    const int b = bh >> 3, h = bh & 7;
    const int t = threadIdx.x;
    const int base = slice * RROWS;

    for (int i = t; i < Lk; i += 256)
        sKey[i] = g_Key[bh*Lk + i];
    __syncthreads();

    const unsigned long long my = sKey[base + t];
    int cnt = 0;
    #pragma unroll 8
    for (int j = 0; j < Lk; j++)
        cnt += (sKey[j] > my);
    sR[t] = cnt;
    __syncthreads();

    const float* src = g_Otmp + ((size_t)bh * Lk + base) * Dk;
    for (int w = t; w < RROWS * (Dk/4); w += 256) {
        int lr = w >> 4;
        int c  = (w & 15) * 4;
        float4 v = *(const float4*)(src + lr*Dk + c);
        int rr = sR[lr];
        *(float4*)(out + (((size_t)b*Lk + rr)*Hk + h)*Dk + c) = v;
    }
}

// ---------------------------------------------------------------------------
extern "C" void kernel_launch(void* const* d_in, const int* in_sizes, int n_in,
                              void* d_out, int out_size)
{
    (void)in_sizes; (void)n_in; (void)out_size;
    const float* Q = (const float*)d_in[0];
    const float* K = (const float*)d_in[1];
    const float* V = (const float*)d_in[2];
    float* out = (float*)d_out;

    cudaFuncSetAttribute(k_attn, cudaFuncAttributeMaxDynamicSharedMemorySize, SMEM_BYTES);

    k_attn<<<NBH * (Lk / TQ), NTHREADS, SMEM_BYTES>>>(Q, K, V);
    k_rank_scatter<<<NBH * 8, 256>>>(out);
}

// round 7
// speedup vs baseline: 3.0979x; 1.3880x over previous
#include <cuda_runtime.h>
#include <cstdint>

typedef uint32_t u32;

// Problem constants
#define Bk 2
#define Lk 2048
#define Sk 2048
#define Hk 8
#define Ek 64
#define Dk 64
#define NBH (Bk*Hk)

#define TQ 128            // queries per CTA
#define TS 64             // keys per chunk
#define NCHUNK (Sk/TS)    // 32
#define NTHREADS 256

// smem row strides (floats)
#define QP 76   // 304B rows: 16B-aligned, frag-load banks 12g+tg all distinct
#define KP 76   // K stored [s][e]; same properties
#define VP 72   // V stored [s][d]; frag-load banks 8tg+g distinct; 288B aligned
#define PP 68

// smem float offsets
#define O_QHI 0
#define O_QLO (O_QHI + TQ*QP)
#define O_KHI (O_QLO + TQ*QP)
#define O_KLO (O_KHI + TS*KP)
#define O_VHI (O_KLO + TS*KP)
#define O_VLO (O_VHI + TS*VP)
#define O_P   (O_VLO + TS*VP)
#define O_DEN (O_P + TQ*PP)
#define O_MX  (O_DEN + 2*TQ)
#define O_MXI (O_MX + 2*TQ)
#define O_INV (O_MXI + 2*TQ)
#define O_KS  (O_INV + TQ)       // [16][64] partials
#define O_KSUM (O_KS + 16*64)    // [64]
#define SMEM_FLOATS (O_KSUM + 64)
#define SMEM_BYTES  (SMEM_FLOATS * 4)

// Scratch
__device__ float g_Otmp[(size_t)NBH * Lk * Dk];
__device__ unsigned long long g_Key[NBH * Lk];

__device__ __forceinline__ float hi32(float x) {
    return __uint_as_float(__float_as_uint(x) & 0xFFFFE000u);
}

// m16n8k8 tf32 mma: D += A*B. a: 4 regs, b: 2 regs, d: 4 fp32.
__device__ __forceinline__ void mma8(float* d, const u32* a, u32 b0, u32 b1) {
    asm volatile(
        "mma.sync.aligned.m16n8k8.row.col.f32.tf32.tf32.f32 "
        "{%0,%1,%2,%3}, {%4,%5,%6,%7}, {%8,%9}, {%0,%1,%2,%3};"
        : "+f"(d[0]), "+f"(d[1]), "+f"(d[2]), "+f"(d[3])
        : "r"(a[0]), "r"(a[1]), "r"(a[2]), "r"(a[3]), "r"(b0), "r"(b1));
}

// ---------------------------------------------------------------------------
// Kernel 1: HMMA tf32 (3-term fp32-split) flash attention.
// Conflict-free smem (no transpose stores), register prefetch of next chunk.
// Exact M_sp: mean via q.Ksum, max via tf32-argmax + exact fp32 re-dot.
// ---------------------------------------------------------------------------
__global__ __launch_bounds__(NTHREADS, 1)
void k_attn(const float* __restrict__ Qg,
            const float* __restrict__ Kg,
            const float* __restrict__ Vg)
{
    extern __shared__ float sm[];
    const int tile = blockIdx.x & 15;
    const int bh   = blockIdx.x >> 4;
    const int b = bh >> 3, h = bh & 7;
    const int q0 = tile * TQ;
    const int tid  = threadIdx.x;
    const int lane = tid & 31, wid = tid >> 5;
    const int wm = wid >> 1, wn = wid & 1;
    const int g = lane >> 2, tg = lane & 3;

    const int r0 = tid >> 4;             // 0..15
    const int c0 = (tid & 15) << 2;      // 0..60

    // ---- load + split Q tile (persistent, [q][e] hi/lo, float4 stores) ----
    #pragma unroll
    for (int i = 0; i < 8; i++) {
        int r = r0 + 16*i;               // 0..127
        float4 v = *(const float4*)(Qg + ((size_t)((b*Lk + q0 + r)*Hk + h))*Ek + c0);
        float4 hi = make_float4(hi32(v.x), hi32(v.y), hi32(v.z), hi32(v.w));
        float4 lo = make_float4(v.x-hi.x, v.y-hi.y, v.z-hi.z, v.w-hi.w);
        *(float4*)(sm + O_QHI + r*QP + c0) = hi;
        *(float4*)(sm + O_QLO + r*QP + c0) = lo;
    }

    float D2[2][4][4];
    #pragma unroll
    for (int mt = 0; mt < 2; mt++)
        #pragma unroll
        for (int nt = 0; nt < 4; nt++)
            #pragma unroll
            for (int r = 0; r < 4; r++) D2[mt][nt][r] = 0.f;

    float den_p[2][2] = {{0.f,0.f},{0.f,0.f}};
    float mx_p[2][2]  = {{-1e30f,-1e30f},{-1e30f,-1e30f}};
    int   mxi_p[2][2] = {{0,0},{0,0}};
    float ksum_r[4]   = {0.f,0.f,0.f,0.f};

    // ---- prefetch chunk 0 into regs ----
    float4 kbuf[4], vbuf[4];
    #pragma unroll
    for (int i = 0; i < 4; i++) {
        int r = r0 + 16*i;               // 0..63
        kbuf[i] = *(const float4*)(Kg + ((size_t)((b*Sk + r)*Hk + h))*Ek + c0);
        vbuf[i] = *(const float4*)(Vg + ((size_t)((b*Sk + r)*Hk + h))*Dk + c0);
    }

    for (int ch = 0; ch < NCHUNK; ch++) {
        __syncthreads();   // prev GEMM reads done before K/V overwrite

        // ---- store K chunk [s][e] hi/lo (float4, conflict-free) + Ksum ----
        #pragma unroll
        for (int i = 0; i < 4; i++) {
            int r = r0 + 16*i;
            float4 v = kbuf[i];
            ksum_r[0] += v.x; ksum_r[1] += v.y; ksum_r[2] += v.z; ksum_r[3] += v.w;
            float4 hi = make_float4(hi32(v.x), hi32(v.y), hi32(v.z), hi32(v.w));
            float4 lo = make_float4(v.x-hi.x, v.y-hi.y, v.z-hi.z, v.w-hi.w);
            *(float4*)(sm + O_KHI + r*KP + c0) = hi;
            *(float4*)(sm + O_KLO + r*KP + c0) = lo;
        }
        // ---- store V chunk [s][d] hi/lo (float4) ----
        #pragma unroll
        for (int i = 0; i < 4; i++) {
            int r = r0 + 16*i;
            float4 v = vbuf[i];
            float4 hi = make_float4(hi32(v.x), hi32(v.y), hi32(v.z), hi32(v.w));
            float4 lo = make_float4(v.x-hi.x, v.y-hi.y, v.z-hi.z, v.w-hi.w);
            *(float4*)(sm + O_VHI + r*VP + c0) = hi;
            *(float4*)(sm + O_VLO + r*VP + c0) = lo;
        }
        __syncthreads();

        // ---- prefetch next chunk (overlaps with GEMMs below) ----
        if (ch + 1 < NCHUNK) {
            const int s1 = (ch + 1) * TS;
            #pragma unroll
            for (int i = 0; i < 4; i++) {
                int r = s1 + r0 + 16*i;
                kbuf[i] = *(const float4*)(Kg + ((size_t)((b*Sk + r)*Hk + h))*Ek + c0);
                vbuf[i] = *(const float4*)(Vg + ((size_t)((b*Sk + r)*Hk + h))*Dk + c0);
            }
        }

        // ---- GEMM1: scores(q,s) = Q.K^T via 3-term split ----
        float D1[2][4][4];
        #pragma unroll
        for (int mt = 0; mt < 2; mt++)
            #pragma unroll
            for (int nt = 0; nt < 4; nt++)
                #pragma unroll
                for (int r = 0; r < 4; r++) D1[mt][nt][r] = 0.f;

        #pragma unroll
        for (int ks = 0; ks < 8; ks++) {
            const int e0 = ks << 3;
            u32 ahi[2][4], alo[2][4];
            #pragma unroll
            for (int mt = 0; mt < 2; mt++) {
                const int qr = 32*wm + 16*mt;
                ahi[mt][0] = __float_as_uint(sm[O_QHI + (qr+g  )*QP + e0 + tg]);
                ahi[mt][1] = __float_as_uint(sm[O_QHI + (qr+g+8)*QP + e0 + tg]);
                ahi[mt][2] = __float_as_uint(sm[O_QHI + (qr+g  )*QP + e0 + tg+4]);
                ahi[mt][3] = __float_as_uint(sm[O_QHI + (qr+g+8)*QP + e0 + tg+4]);
                alo[mt][0] = __float_as_uint(sm[O_QLO + (qr+g  )*QP + e0 + tg]);
                alo[mt][1] = __float_as_uint(sm[O_QLO + (qr+g+8)*QP + e0 + tg]);
                alo[mt][2] = __float_as_uint(sm[O_QLO + (qr+g  )*QP + e0 + tg+4]);
                alo[mt][3] = __float_as_uint(sm[O_QLO + (qr+g+8)*QP + e0 + tg+4]);
            }
            #pragma unroll
            for (int nt = 0; nt < 4; nt++) {
                const int scol = 32*wn + 8*nt;
                u32 bh0 = __float_as_uint(sm[O_KHI + (scol+g)*KP + e0 + tg]);
                u32 bh1 = __float_as_uint(sm[O_KHI + (scol+g)*KP + e0 + tg+4]);
                u32 bl0 = __float_as_uint(sm[O_KLO + (scol+g)*KP + e0 + tg]);
                u32 bl1 = __float_as_uint(sm[O_KLO + (scol+g)*KP + e0 + tg+4]);
                #pragma unroll
                for (int mt = 0; mt < 2; mt++) {
                    mma8(D1[mt][nt], ahi[mt], bh0, bh1);
                    mma8(D1[mt][nt], alo[mt], bh0, bh1);
                    mma8(D1[mt][nt], ahi[mt], bl0, bl1);
                }
            }
        }

        // ---- softmax + argmax/den stats + P -> smem ----
        const int s0 = ch * TS;
        #pragma unroll
        for (int mt = 0; mt < 2; mt++) {
            const int qr = 32*wm + 16*mt;
            #pragma unroll
            for (int nt = 0; nt < 4; nt++) {
                const int scol = 32*wn + 8*nt + 2*tg;
                const int sglob = s0 + scol;
                float s00 = D1[mt][nt][0], s01 = D1[mt][nt][1];
                float s10 = D1[mt][nt][2], s11 = D1[mt][nt][3];
                float m0 = fmaxf(s00, s01), m1 = fmaxf(s10, s11);
                if (m0 > mx_p[mt][0]) { mx_p[mt][0] = m0; mxi_p[mt][0] = sglob + (s01 > s00); }
                if (m1 > mx_p[mt][1]) { mx_p[mt][1] = m1; mxi_p[mt][1] = sglob + (s11 > s10); }
                float p00 = __expf(s00 * 0.125f), p01 = __expf(s01 * 0.125f);
                float p10 = __expf(s10 * 0.125f), p11 = __expf(s11 * 0.125f);
                den_p[mt][0] += p00 + p01;
                den_p[mt][1] += p10 + p11;
                *(float2*)(sm + O_P + (qr+g  )*PP + scol) = make_float2(p00, p01);
                *(float2*)(sm + O_P + (qr+g+8)*PP + scol) = make_float2(p10, p11);
            }
        }
        __syncthreads();

        // ---- GEMM2: D2 += P.V via 3-term split (P split in regs) ----
        #pragma unroll
        for (int ks = 0; ks < 8; ks++) {
            const int sb2 = ks << 3;
            u32 phi[2][4], plo[2][4];
            #pragma unroll
            for (int mt = 0; mt < 2; mt++) {
                const int qr = 32*wm + 16*mt;
                float p0 = sm[O_P + (qr+g  )*PP + sb2 + tg];
                float p1 = sm[O_P + (qr+g+8)*PP + sb2 + tg];
                float p2 = sm[O_P + (qr+g  )*PP + sb2 + tg+4];
                float p3 = sm[O_P + (qr+g+8)*PP + sb2 + tg+4];
                float h0 = hi32(p0), h1 = hi32(p1), h2 = hi32(p2), h3 = hi32(p3);
                phi[mt][0] = __float_as_uint(h0); plo[mt][0] = __float_as_uint(p0 - h0);
                phi[mt][1] = __float_as_uint(h1); plo[mt][1] = __float_as_uint(p1 - h1);
                phi[mt][2] = __float_as_uint(h2); plo[mt][2] = __float_as_uint(p2 - h2);
                phi[mt][3] = __float_as_uint(h3); plo[mt][3] = __float_as_uint(p3 - h3);
            }
            #pragma unroll
            for (int nt = 0; nt < 4; nt++) {
                const int dcol = 32*wn + 8*nt;
                u32 bh0 = __float_as_uint(sm[O_VHI + (sb2+tg  )*VP + dcol + g]);
                u32 bh1 = __float_as_uint(sm[O_VHI + (sb2+tg+4)*VP + dcol + g]);
                u32 bl0 = __float_as_uint(sm[O_VLO + (sb2+tg  )*VP + dcol + g]);
                u32 bl1 = __float_as_uint(sm[O_VLO + (sb2+tg+4)*VP + dcol + g]);
                #pragma unroll
                for (int mt = 0; mt < 2; mt++) {
                    mma8(D2[mt][nt], phi[mt], bh0, bh1);
                    mma8(D2[mt][nt], plo[mt], bh0, bh1);
                    mma8(D2[mt][nt], phi[mt], bl0, bl1);
                }
            }
        }
    }

    // ---- Ksum reduction: [16 row-groups][64 cols] -> Ksum[64] ----
    *(float4*)(sm + O_KS + r0*64 + c0) =
        make_float4(ksum_r[0], ksum_r[1], ksum_r[2], ksum_r[3]);

    // ---- den/max/idx: reduce over tg lanes, publish per wn ----
    #pragma unroll
    for (int mt = 0; mt < 2; mt++)
        #pragma unroll
        for (int r = 0; r < 2; r++) {
            float d = den_p[mt][r], mx = mx_p[mt][r];
            int idx = mxi_p[mt][r];
            #pragma unroll
            for (int o = 1; o < 4; o <<= 1) {
                d += __shfl_xor_sync(0xffffffffu, d, o);
                float om = __shfl_xor_sync(0xffffffffu, mx, o);
                int   oi = __shfl_xor_sync(0xffffffffu, idx, o);
                if (om > mx) { mx = om; idx = oi; }
            }
            if (tg == 0) {
                int q = 32*wm + 16*mt + g + 8*r;
                sm[O_DEN + wn*TQ + q] = d;
                sm[O_MX  + wn*TQ + q] = mx;
                sm[O_MXI + wn*TQ + q] = __int_as_float(idx);
            }
        }
    __syncthreads();

    if (tid < 64) {
        float s = 0.f;
        #pragma unroll
        for (int gr = 0; gr < 16; gr++) s += sm[O_KS + gr*64 + tid];
        sm[O_KSUM + tid] = s;
    }
    __syncthreads();

    // ---- exact M_sp per query: refined max + q.Ksum mean ----
    if (tid < TQ) {
        const int q = tid;
        float den = sm[O_DEN + q] + sm[O_DEN + TQ + q];
        sm[O_INV + q] = 1.0f / den;
        float mx0 = sm[O_MX + q], mx1 = sm[O_MX + TQ + q];
        int idx = (mx1 > mx0) ? __float_as_int(sm[O_MXI + TQ + q])
                              : __float_as_int(sm[O_MXI + q]);
        const float* krow = Kg + ((size_t)((b*Sk + idx)*Hk + h))*Ek;
        float dot = 0.f, rs = 0.f;
        #pragma unroll 8
        for (int e = 0; e < Ek; e++) {
            float qv = sm[O_QHI + q*QP + e] + sm[O_QLO + q*QP + e];  // exact fp32
            dot = fmaf(qv, krow[e], dot);
            rs  = fmaf(qv, sm[O_KSUM + e], rs);
        }
        float msp = dot - rs * (1.0f / (float)Sk);
        int bi = __float_as_int(msp);
        unsigned u = (unsigned)bi ^ ((bi < 0) ? 0xFFFFFFFFu : 0x80000000u);
        int l = q0 + q;
        g_Key[bh*Lk + l] = ((unsigned long long)u << 32) | (unsigned)(~l);
    }
    __syncthreads();

    // ---- epilogue: normalize + write Otmp ----
    float* dst = g_Otmp + ((size_t)bh * Lk + q0) * Dk;
    #pragma unroll
    for (int mt = 0; mt < 2; mt++) {
        const int qr = 32*wm + 16*mt;
        float inv0 = sm[O_INV + qr + g];
        float inv1 = sm[O_INV + qr + g + 8];
        #pragma unroll
        for (int nt = 0; nt < 4; nt++) {
            const int dcol = 32*wn + 8*nt + 2*tg;
            *(float2*)(dst + (size_t)(qr+g  )*Dk + dcol) =
                make_float2(D2[mt][nt][0]*inv0, D2[mt][nt][1]*inv0);
            *(float2*)(dst + (size_t)(qr+g+8)*Dk + dcol) =
                make_float2(D2[mt][nt][2]*inv1, D2[mt][nt][3]*inv1);
        }
    }
}

// ---------------------------------------------------------------------------
// Kernel 2: rank via counting on packed u64 keys + fused scatter.
// ---------------------------------------------------------------------------
#define RROWS 256
__global__ __launch_bounds__(256)
void k_rank_scatter(float* __restrict__ out)
{
    __shared__ unsigned long long sKey[Lk];
    __shared__ int sR[RROWS];
    const int slice = blockIdx.x & 7;
    const int bh    = blockIdx.x >> 3;
    const int b = bh >> 3, h = bh & 7;
    const int t = threadIdx.x;
    const int base = slice * RROWS;

    for (int i = t; i < Lk; i += 256)
        sKey[i] = g_Key[bh*Lk + i];
    __syncthreads();

    const unsigned long long my = sKey[base + t];
    int cnt = 0;
    #pragma unroll 8
    for (int j = 0; j < Lk; j++)
        cnt += (sKey[j] > my);
    sR[t] = cnt;
    __syncthreads();

    const float* src = g_Otmp + ((size_t)bh * Lk + base) * Dk;
    for (int w = t; w < RROWS * (Dk/4); w += 256) {
        int lr = w >> 4;
        int c  = (w & 15) * 4;
        float4 v = *(const float4*)(src + lr*Dk + c);
        int rr = sR[lr];
        *(float4*)(out + (((size_t)b*Lk + rr)*Hk + h)*Dk + c) = v;
    }
}

// ---------------------------------------------------------------------------
extern "C" void kernel_launch(void* const* d_in, const int* in_sizes, int n_in,
                              void* d_out, int out_size)
{
    (void)in_sizes; (void)n_in; (void)out_size;
    const float* Q = (const float*)d_in[0];
    const float* K = (const float*)d_in[1];
    const float* V = (const float*)d_in[2];
    float* out = (float*)d_out;

    cudaFuncSetAttribute(k_attn, cudaFuncAttributeMaxDynamicSharedMemorySize, SMEM_BYTES);

    k_attn<<<NBH * (Lk / TQ), NTHREADS, SMEM_BYTES>>>(Q, K, V);
    k_rank_scatter<<<NBH * 8, 256>>>(out);
}

// round 8
// speedup vs baseline: 4.6299x; 1.4945x over previous
#include <cuda_runtime.h>
#include <cuda_fp16.h>
#include <cstdint>

typedef uint32_t u32;

// Problem constants
#define Bk 2
#define Lk 2048
#define Sk 2048
#define Hk 8
#define Ek 64
#define Dk 64
#define NBH (Bk*Hk)

#define TQ 128            // queries per CTA
#define TS 64             // keys per chunk
#define NCHUNK (Sk/TS)    // 32
#define NTHREADS 256

// fp16 smem row strides (fp16 units): 72 -> 144B rows, conflict-free ldmatrix
#define QP2 72
#define KP2 72
#define VP2 72
#define PP2 72

// smem fp16-unit offsets
#define O_QHI 0
#define O_QLO (O_QHI + TQ*QP2)        // 9216
#define O_KHI (O_QLO + TQ*QP2)        // 18432
#define O_KLO (O_KHI + TS*KP2)        // 23040
#define O_VHI (O_KLO + TS*KP2)        // 27648
#define O_VLO (O_VHI + TS*VP2)        // 32256
#define O_PHI (O_VLO + TS*VP2)        // 36864
#define O_PLO (O_PHI + TQ*PP2)        // 46080
#define SMEM_HALFS (O_PLO + TQ*PP2)   // 55296
#define SMEM_BYTES (SMEM_HALFS * 2)   // 110592

// stats alias (floats) inside the P region (valid only after main loop)
#define S_DEN 0          // [2][128]
#define S_MX  256        // [2][128]
#define S_MXI 512        // [2][128]
#define S_INV 768        // [128]
#define S_KS  896        // [16][64]
#define S_KSUM 1920      // [64]

// Scratch
__device__ float g_Otmp[(size_t)NBH * Lk * Dk];
__device__ unsigned long long g_Key[NBH * Lk];

// fp16 mma m16n8k16: D += A*B (f32 accum)
__device__ __forceinline__ void mma16(float* d, u32 a0, u32 a1, u32 a2, u32 a3,
                                      u32 b0, u32 b1) {
    asm volatile(
        "mma.sync.aligned.m16n8k16.row.col.f32.f16.f16.f32 "
        "{%0,%1,%2,%3}, {%4,%5,%6,%7}, {%8,%9}, {%0,%1,%2,%3};"
        : "+f"(d[0]), "+f"(d[1]), "+f"(d[2]), "+f"(d[3])
        : "r"(a0), "r"(a1), "r"(a2), "r"(a3), "r"(b0), "r"(b1));
}

#define LDSM_X4(r0,r1,r2,r3,addr) \
    asm volatile("ldmatrix.sync.aligned.m8n8.x4.shared.b16 {%0,%1,%2,%3}, [%4];" \
        : "=r"(r0), "=r"(r1), "=r"(r2), "=r"(r3) : "r"(addr))
#define LDSM_X2(r0,r1,addr) \
    asm volatile("ldmatrix.sync.aligned.m8n8.x2.shared.b16 {%0,%1}, [%2];" \
        : "=r"(r0), "=r"(r1) : "r"(addr))
#define LDSM_X2T(r0,r1,addr) \
    asm volatile("ldmatrix.sync.aligned.m8n8.x2.trans.shared.b16 {%0,%1}, [%2];" \
        : "=r"(r0), "=r"(r1) : "r"(addr))

__device__ __forceinline__ u32 smem_u32(const void* p) {
    u32 a; asm("{ .reg .u64 t; cvta.to.shared.u64 t, %1; cvt.u32.u64 %0, t; }" : "=r"(a) : "l"(p));
    return a;
}

// split fp32 -> (h1, h2) fp16 pair, h1+h2 ~ x to 2^-22
__device__ __forceinline__ void split16(float v, __half& h, __half& l) {
    h = __float2half_rn(v);
    l = __float2half_rn(v - __half2float(h));
}

// ---------------------------------------------------------------------------
// Kernel 1: fp16-split (3-term m16n8k16) flash attention, occupancy 2.
// Exact M_sp: mean via q.Ksum; max via approx-argmax + exact fp32 re-dot
// (both dots use gmem Q/K for exactness).
// ---------------------------------------------------------------------------
__global__ __launch_bounds__(NTHREADS, 2)
void k_attn(const float* __restrict__ Qg,
            const float* __restrict__ Kg,
            const float* __restrict__ Vg)
{
    extern __shared__ __half smh[];
    float* st = (float*)(smh + O_PHI);     // stats alias (post-loop only)
    const u32 sb = smem_u32(smh);

    const int tile = blockIdx.x & 15;
    const int bh   = blockIdx.x >> 4;
    const int b = bh >> 3, h = bh & 7;
    const int q0 = tile * TQ;
    const int tid  = threadIdx.x;
    const int lane = tid & 31, wid = tid >> 5;
    const int wm = wid >> 1, wn = wid & 1;
    const int g = lane >> 2, tg = lane & 3;

    const int r0 = tid >> 4;             // 0..15
    const int c0 = (tid & 15) << 2;      // 0..60

    // ldmatrix per-lane address components
    const int aRow = lane & 15;          // A-frag row within 16
    const int aCol = (lane >> 4) << 3;   // A-frag k-block offset (0 or 8)
    const int bRowK = lane & 7;          // K B-frag row (s within 8)
    const int bColK = lane & 8;          // K B-frag k-block (0 or 8)
    const int vRow = lane & 15;          // V B-frag row (s within 16)

    // ---- load + split Q tile (persistent, [q][e] fp16 hi/lo) ----
    #pragma unroll
    for (int i = 0; i < 8; i++) {
        int r = r0 + 16*i;
        float4 v = *(const float4*)(Qg + ((size_t)((b*Lk + q0 + r)*Hk + h))*Ek + c0);
        __half hx, lx, hy, ly, hz, lz, hw, lw;
        split16(v.x, hx, lx); split16(v.y, hy, ly);
        split16(v.z, hz, lz); split16(v.w, hw, lw);
        *(__half2*)(smh + O_QHI + r*QP2 + c0)     = __halves2half2(hx, hy);
        *(__half2*)(smh + O_QHI + r*QP2 + c0 + 2) = __halves2half2(hz, hw);
        *(__half2*)(smh + O_QLO + r*QP2 + c0)     = __halves2half2(lx, ly);
        *(__half2*)(smh + O_QLO + r*QP2 + c0 + 2) = __halves2half2(lz, lw);
    }

    float D2[2][4][4];
    #pragma unroll
    for (int mt = 0; mt < 2; mt++)
        #pragma unroll
        for (int nt = 0; nt < 4; nt++)
            #pragma unroll
            for (int r = 0; r < 4; r++) D2[mt][nt][r] = 0.f;

    float den_p[2][2] = {{0.f,0.f},{0.f,0.f}};
    float mx_p[2][2]  = {{-1e30f,-1e30f},{-1e30f,-1e30f}};
    int   mxi_p[2][2] = {{0,0},{0,0}};
    float ksum_r[4]   = {0.f,0.f,0.f,0.f};

    for (int ch = 0; ch < NCHUNK; ch++) {
        const int s0 = ch * TS;
        __syncthreads();   // all warps past prev GEMM2 before K/V/P overwrite

        // ---- K chunk: load fp32, Ksum, split -> smem [s][e] ----
        #pragma unroll
        for (int i = 0; i < 4; i++) {
            int r = r0 + 16*i;
            float4 v = *(const float4*)(Kg + ((size_t)((b*Sk + s0 + r)*Hk + h))*Ek + c0);
            ksum_r[0] += v.x; ksum_r[1] += v.y; ksum_r[2] += v.z; ksum_r[3] += v.w;
            __half hx, lx, hy, ly, hz, lz, hw, lw;
            split16(v.x, hx, lx); split16(v.y, hy, ly);
            split16(v.z, hz, lz); split16(v.w, hw, lw);
            *(__half2*)(smh + O_KHI + r*KP2 + c0)     = __halves2half2(hx, hy);
            *(__half2*)(smh + O_KHI + r*KP2 + c0 + 2) = __halves2half2(hz, hw);
            *(__half2*)(smh + O_KLO + r*KP2 + c0)     = __halves2half2(lx, ly);
            *(__half2*)(smh + O_KLO + r*KP2 + c0 + 2) = __halves2half2(lz, lw);
        }
        // ---- V chunk: load, split -> smem [s][d] ----
        #pragma unroll
        for (int i = 0; i < 4; i++) {
            int r = r0 + 16*i;
            float4 v = *(const float4*)(Vg + ((size_t)((b*Sk + s0 + r)*Hk + h))*Dk + c0);
            __half hx, lx, hy, ly, hz, lz, hw, lw;
            split16(v.x, hx, lx); split16(v.y, hy, ly);
            split16(v.z, hz, lz); split16(v.w, hw, lw);
            *(__half2*)(smh + O_VHI + r*VP2 + c0)     = __halves2half2(hx, hy);
            *(__half2*)(smh + O_VHI + r*VP2 + c0 + 2) = __halves2half2(hz, hw);
            *(__half2*)(smh + O_VLO + r*VP2 + c0)     = __halves2half2(lx, ly);
            *(__half2*)(smh + O_VLO + r*VP2 + c0 + 2) = __halves2half2(lz, lw);
        }
        __syncthreads();

        // ---- GEMM1: scores(q,s) = Q.K^T, 3-term fp16 split ----
        float D1[2][4][4];
        #pragma unroll
        for (int mt = 0; mt < 2; mt++)
            #pragma unroll
            for (int nt = 0; nt < 4; nt++)
                #pragma unroll
                for (int r = 0; r < 4; r++) D1[mt][nt][r] = 0.f;

        #pragma unroll
        for (int ks = 0; ks < 4; ks++) {
            const int e0 = ks << 4;
            u32 ah[2][4], al[2][4];
            #pragma unroll
            for (int mt = 0; mt < 2; mt++) {
                const int qr = 32*wm + 16*mt;
                u32 adr = sb + 2*(O_QHI + (qr + aRow)*QP2 + e0 + aCol);
                LDSM_X4(ah[mt][0], ah[mt][1], ah[mt][2], ah[mt][3], adr);
                adr = sb + 2*(O_QLO + (qr + aRow)*QP2 + e0 + aCol);
                LDSM_X4(al[mt][0], al[mt][1], al[mt][2], al[mt][3], adr);
            }
            #pragma unroll
            for (int nt = 0; nt < 4; nt++) {
                const int scol = 32*wn + 8*nt;
                u32 bh0, bh1, bl0, bl1;
                u32 adr = sb + 2*(O_KHI + (scol + bRowK)*KP2 + e0 + bColK);
                LDSM_X2(bh0, bh1, adr);
                adr = sb + 2*(O_KLO + (scol + bRowK)*KP2 + e0 + bColK);
                LDSM_X2(bl0, bl1, adr);
                #pragma unroll
                for (int mt = 0; mt < 2; mt++) {
                    mma16(D1[mt][nt], ah[mt][0], ah[mt][1], ah[mt][2], ah[mt][3], bh0, bh1);
                    mma16(D1[mt][nt], al[mt][0], al[mt][1], al[mt][2], al[mt][3], bh0, bh1);
                    mma16(D1[mt][nt], ah[mt][0], ah[mt][1], ah[mt][2], ah[mt][3], bl0, bl1);
                }
            }
        }

        // ---- softmax + argmax/den stats + P (fp16 split) -> smem ----
        #pragma unroll
        for (int mt = 0; mt < 2; mt++) {
            const int qr = 32*wm + 16*mt;
            #pragma unroll
            for (int nt = 0; nt < 4; nt++) {
                const int scol = 32*wn + 8*nt + 2*tg;
                const int sglob = s0 + scol;
                float s00 = D1[mt][nt][0], s01 = D1[mt][nt][1];
                float s10 = D1[mt][nt][2], s11 = D1[mt][nt][3];
                float m0 = fmaxf(s00, s01), m1 = fmaxf(s10, s11);
                if (m0 > mx_p[mt][0]) { mx_p[mt][0] = m0; mxi_p[mt][0] = sglob + (s01 > s00); }
                if (m1 > mx_p[mt][1]) { mx_p[mt][1] = m1; mxi_p[mt][1] = sglob + (s11 > s10); }
                float p00 = __expf(s00 * 0.125f), p01 = __expf(s01 * 0.125f);
                float p10 = __expf(s10 * 0.125f), p11 = __expf(s11 * 0.125f);
                den_p[mt][0] += p00 + p01;
                den_p[mt][1] += p10 + p11;
                __half h00, l00, h01, l01, h10, l10, h11, l11;
                split16(p00, h00, l00); split16(p01, h01, l01);
                split16(p10, h10, l10); split16(p11, h11, l11);
                *(__half2*)(smh + O_PHI + (qr+g  )*PP2 + scol) = __halves2half2(h00, h01);
                *(__half2*)(smh + O_PHI + (qr+g+8)*PP2 + scol) = __halves2half2(h10, h11);
                *(__half2*)(smh + O_PLO + (qr+g  )*PP2 + scol) = __halves2half2(l00, l01);
                *(__half2*)(smh + O_PLO + (qr+g+8)*PP2 + scol) = __halves2half2(l10, l11);
            }
        }
        __syncthreads();

        // ---- GEMM2: D2 += P.V, 3-term fp16 split ----
        #pragma unroll
        for (int ks = 0; ks < 4; ks++) {
            const int sb2 = ks << 4;
            u32 ah[2][4], al[2][4];
            #pragma unroll
            for (int mt = 0; mt < 2; mt++) {
                const int qr = 32*wm + 16*mt;
                u32 adr = sb + 2*(O_PHI + (qr + aRow)*PP2 + sb2 + aCol);
                LDSM_X4(ah[mt][0], ah[mt][1], ah[mt][2], ah[mt][3], adr);
                adr = sb + 2*(O_PLO + (qr + aRow)*PP2 + sb2 + aCol);
                LDSM_X4(al[mt][0], al[mt][1], al[mt][2], al[mt][3], adr);
            }
            #pragma unroll
            for (int nt = 0; nt < 4; nt++) {
                const int dcol = 32*wn + 8*nt;
                u32 bh0, bh1, bl0, bl1;
                u32 adr = sb + 2*(O_VHI + (sb2 + vRow)*VP2 + dcol);
                LDSM_X2T(bh0, bh1, adr);
                adr = sb + 2*(O_VLO + (sb2 + vRow)*VP2 + dcol);
                LDSM_X2T(bl0, bl1, adr);
                #pragma unroll
                for (int mt = 0; mt < 2; mt++) {
                    mma16(D2[mt][nt], ah[mt][0], ah[mt][1], ah[mt][2], ah[mt][3], bh0, bh1);
                    mma16(D2[mt][nt], al[mt][0], al[mt][1], al[mt][2], al[mt][3], bh0, bh1);
                    mma16(D2[mt][nt], ah[mt][0], ah[mt][1], ah[mt][2], ah[mt][3], bl0, bl1);
                }
            }
        }
    }

    __syncthreads();   // main loop done: P region becomes stats scratch

    // ---- Ksum partials -> stats region ----
    *(float4*)(st + S_KS + r0*64 + c0) =
        make_float4(ksum_r[0], ksum_r[1], ksum_r[2], ksum_r[3]);

    // ---- den/max/idx: reduce over tg lanes, publish per wn ----
    #pragma unroll
    for (int mt = 0; mt < 2; mt++)
        #pragma unroll
        for (int r = 0; r < 2; r++) {
            float d = den_p[mt][r], mx = mx_p[mt][r];
            int idx = mxi_p[mt][r];
            #pragma unroll
            for (int o = 1; o < 4; o <<= 1) {
                d += __shfl_xor_sync(0xffffffffu, d, o);
                float om = __shfl_xor_sync(0xffffffffu, mx, o);
                int   oi = __shfl_xor_sync(0xffffffffu, idx, o);
                if (om > mx) { mx = om; idx = oi; }
            }
            if (tg == 0) {
                int q = 32*wm + 16*mt + g + 8*r;
                st[S_DEN + wn*TQ + q] = d;
                st[S_MX  + wn*TQ + q] = mx;
                st[S_MXI + wn*TQ + q] = __int_as_float(idx);
            }
        }
    __syncthreads();

    if (tid < 64) {
        float s = 0.f;
        #pragma unroll
        for (int gr = 0; gr < 16; gr++) s += st[S_KS + gr*64 + tid];
        st[S_KSUM + tid] = s;
    }
    __syncthreads();

    // ---- exact M_sp per query (gmem Q/K dots) ----
    if (tid < TQ) {
        const int q = tid;
        float den = st[S_DEN + q] + st[S_DEN + TQ + q];
        st[S_INV + q] = 1.0f / den;
        float mx0 = st[S_MX + q], mx1 = st[S_MX + TQ + q];
        int idx = (mx1 > mx0) ? __float_as_int(st[S_MXI + TQ + q])
                              : __float_as_int(st[S_MXI + q]);
        const float* qrow = Qg + ((size_t)((b*Lk + q0 + q)*Hk + h))*Ek;
        const float* krow = Kg + ((size_t)((b*Sk + idx)*Hk + h))*Ek;
        float dot = 0.f, rs = 0.f;
        #pragma unroll 8
        for (int e = 0; e < Ek; e++) {
            float qv = qrow[e];
            dot = fmaf(qv, krow[e], dot);
            rs  = fmaf(qv, st[S_KSUM + e], rs);
        }
        float msp = dot - rs * (1.0f / (float)Sk);
        int bi = __float_as_int(msp);
        unsigned u = (unsigned)bi ^ ((bi < 0) ? 0xFFFFFFFFu : 0x80000000u);
        int l = q0 + q;
        g_Key[bh*Lk + l] = ((unsigned long long)u << 32) | (unsigned)(~l);
    }
    __syncthreads();

    // ---- epilogue: normalize + write Otmp ----
    float* dst = g_Otmp + ((size_t)bh * Lk + q0) * Dk;
    #pragma unroll
    for (int mt = 0; mt < 2; mt++) {
        const int qr = 32*wm + 16*mt;
        float inv0 = st[S_INV + qr + g];
        float inv1 = st[S_INV + qr + g + 8];
        #pragma unroll
        for (int nt = 0; nt < 4; nt++) {
            const int dcol = 32*wn + 8*nt + 2*tg;
            *(float2*)(dst + (size_t)(qr+g  )*Dk + dcol) =
                make_float2(D2[mt][nt][0]*inv0, D2[mt][nt][1]*inv0);
            *(float2*)(dst + (size_t)(qr+g+8)*Dk + dcol) =
                make_float2(D2[mt][nt][2]*inv1, D2[mt][nt][3]*inv1);
        }
    }
}

// ---------------------------------------------------------------------------
// Kernel 2: rank via counting on packed u64 keys + fused scatter.
// ---------------------------------------------------------------------------
#define RROWS 256
__global__ __launch_bounds__(256)
void k_rank_scatter(float* __restrict__ out)
{
    __shared__ unsigned long long sKey[Lk];
    __shared__ int sR[RROWS];
    const int slice = blockIdx.x & 7;
    const int bh    = blockIdx.x >> 3;
    const int b = bh >> 3, h = bh & 7;
    const int t = threadIdx.x;
    const int base = slice * RROWS;

    for (int i = t; i < Lk; i += 256)
        sKey[i] = g_Key[bh*Lk + i];
    __syncthreads();

    const unsigned long long my = sKey[base + t];
    int cnt = 0;
    #pragma unroll 8
    for (int j = 0; j < Lk; j++)
        cnt += (sKey[j] > my);
    sR[t] = cnt;
    __syncthreads();

    const float* src = g_Otmp + ((size_t)bh * Lk + base) * Dk;
    for (int w = t; w < RROWS * (Dk/4); w += 256) {
        int lr = w >> 4;
        int c  = (w & 15) * 4;
        float4 v = *(const float4*)(src + lr*Dk + c);
        int rr = sR[lr];
        *(float4*)(out + (((size_t)b*Lk + rr)*Hk + h)*Dk + c) = v;
    }
}

// ---------------------------------------------------------------------------
extern "C" void kernel_launch(void* const* d_in, const int* in_sizes, int n_in,
                              void* d_out, int out_size)
{
    (void)in_sizes; (void)n_in; (void)out_size;
    const float* Q = (const float*)d_in[0];
    const float* K = (const float*)d_in[1];
    const float* V = (const float*)d_in[2];
    float* out = (float*)d_out;

    cudaFuncSetAttribute(k_attn, cudaFuncAttributeMaxDynamicSharedMemorySize, SMEM_BYTES);

    k_attn<<<NBH * (Lk / TQ), NTHREADS, SMEM_BYTES>>>(Q, K, V);
    k_rank_scatter<<<NBH * 8, 256>>>(out);
}